// round 3
// baseline (speedup 1.0000x reference)
#include <cuda_runtime.h>

#define NMAX   100000
#define EMAX   1600000
#define INH    18
#define OUTH   11
#define OUTP   12      // padded to 3x float4
#define NCLASS 40
#define CDIM   51      // NCLASS + OUTH

// ---------------- scratch (device globals; no allocs allowed) ----------------
__device__ float g_deg [NMAX];
__device__ float g_dinv[NMAX];
__device__ float g_sdin[NMAX];
__device__ __align__(16) float g_M [NMAX * OUTP];
__device__ __align__(16) float g_Y1[NMAX * OUTP];
__device__ __align__(16) float g_Y2[NMAX * OUTP];
__device__ float g_W12[INH * OUTH];   // W1 @ W2  [18,11]
__device__ float g_c  [OUTH];         // b1 @ W2  [11]

// vector reduction into global (sm_90+): one 16B L2 atomic instead of 4 scalar
__device__ __forceinline__ void red_add_v4(float* p, float4 v) {
    asm volatile("red.global.add.v4.f32 [%0], {%1, %2, %3, %4};"
                 :: "l"(p), "f"(v.x), "f"(v.y), "f"(v.z), "f"(v.w)
                 : "memory");
}

// ---------------- kernels ----------------

// init scratch (runs every launch; graph-replay safe)
__global__ void k_init(int n) {
    int i = blockIdx.x * blockDim.x + threadIdx.x;
    if (i >= n) return;
    g_deg[i]  = 1.0f;   // self-loop
    g_sdin[i] = 0.0f;
    float4 z = make_float4(0.f, 0.f, 0.f, 0.f);
    float4* y1 = reinterpret_cast<float4*>(&g_Y1[i * OUTP]);
    float4* y2 = reinterpret_cast<float4*>(&g_Y2[i * OUTP]);
    y1[0] = z; y1[1] = z; y1[2] = z;
    y2[0] = z; y2[1] = z; y2[2] = z;
}

// W12 = W1 @ W2 ([18,nh]@[nh,11]); c = b1 @ W2. One block.
__global__ void k_w12(const float* __restrict__ W1, const float* __restrict__ W2,
                      const float* __restrict__ b1, int nh) {
    int t = threadIdx.x;
    if (t < INH * OUTH) {
        int i = t / OUTH, j = t % OUTH;
        float s = 0.f;
        for (int k = 0; k < nh; k++) s += W1[i * nh + k] * W2[k * OUTH + j];
        g_W12[t] = s;
    } else if (t < INH * OUTH + OUTH) {
        int j = t - INH * OUTH;
        float s = 0.f;
        for (int k = 0; k < nh; k++) s += b1[k] * W2[k * OUTH + j];
        g_c[j] = s;
    }
}

// in-degree (+1 from init). edge_index is int32 (JAX x64-disabled default).
__global__ void k_deg(const int* __restrict__ dst, int e) {
    int i = blockIdx.x * blockDim.x + threadIdx.x;
    if (i < e) atomicAdd(&g_deg[dst[i]], 1.0f);
}

// dinv = rsqrt(deg); M = x @ W12 (padded col 11 = 0)
__global__ void k_dinvM(const float* __restrict__ x, int n) {
    __shared__ float w[INH * OUTH];
    for (int t = threadIdx.x; t < INH * OUTH; t += blockDim.x) w[t] = g_W12[t];
    __syncthreads();
    int i = blockIdx.x * blockDim.x + threadIdx.x;
    if (i >= n) return;
    g_dinv[i] = rsqrtf(g_deg[i]);
    float xr[INH];
#pragma unroll
    for (int k = 0; k < INH; k++) xr[k] = x[i * INH + k];
    float o[OUTP];
#pragma unroll
    for (int j = 0; j < OUTH; j++) {
        float s = 0.f;
#pragma unroll
        for (int k = 0; k < INH; k++) s += xr[k] * w[k * OUTH + j];
        o[j] = s;
    }
    o[OUTH] = 0.f;
    float4* mp = reinterpret_cast<float4*>(&g_M[i * OUTP]);
    mp[0] = make_float4(o[0], o[1], o[2],  o[3]);
    mp[1] = make_float4(o[4], o[5], o[6],  o[7]);
    mp[2] = make_float4(o[8], o[9], o[10], o[11]);
}

// one aggregation pass: Yout = A * Min (edges + self-loops).
// pass 0 additionally accumulates sdin[dst] += dinv[src] (for s = A·1).
__global__ void k_agg(int pass, const int* __restrict__ ei, int e, int n) {
    const float* Min  = (pass == 0) ? g_M  : g_Y1;
    float*       Yout = (pass == 0) ? g_Y1 : g_Y2;
    int idx = blockIdx.x * blockDim.x + threadIdx.x;
    int s, d;
    float nrm;
    if (idx < e) {
        s = ei[idx];
        d = ei[e + idx];
        float ds = g_dinv[s];
        float dd = g_dinv[d];
        nrm = ds * dd;
        if (pass == 0) atomicAdd(&g_sdin[d], ds);
    } else if (idx < e + n) {
        s = d = idx - e;              // self-loop
        float di = g_dinv[s];
        nrm = di * di;
    } else {
        return;
    }
    const float4* m = reinterpret_cast<const float4*>(&Min[(size_t)s * OUTP]);
    float4 a = m[0], b = m[1], c = m[2];
    a.x *= nrm; a.y *= nrm; a.z *= nrm; a.w *= nrm;
    b.x *= nrm; b.y *= nrm; b.z *= nrm; b.w *= nrm;
    c.x *= nrm; c.y *= nrm; c.z *= nrm; c.w *= nrm;
    float* y = &Yout[(size_t)d * OUTP];
    red_add_v4(y,     a);
    red_add_v4(y + 4, b);
    red_add_v4(y + 8, c);
}

// epilogue: emb_b = relu(Y2 + s*c + b2);  out = [emb_a, emb_b] @ Wc + bc
__global__ void k_final(const float* __restrict__ emb_a, const float* __restrict__ b2,
                        const float* __restrict__ Wc, const float* __restrict__ bc,
                        float* __restrict__ out, int n) {
    __shared__ float wsm[CDIM * NCLASS];
    __shared__ float bsm[NCLASS];
    __shared__ float csm[OUTH];
    __shared__ float b2sm[OUTH];
    for (int t = threadIdx.x; t < CDIM * NCLASS; t += blockDim.x) wsm[t] = Wc[t];
    if (threadIdx.x < NCLASS) bsm[threadIdx.x] = bc[threadIdx.x];
    if (threadIdx.x < OUTH) { csm[threadIdx.x] = g_c[threadIdx.x]; b2sm[threadIdx.x] = b2[threadIdx.x]; }
    __syncthreads();
    int i = blockIdx.x * blockDim.x + threadIdx.x;
    if (i >= n) return;

    float acc[NCLASS];
#pragma unroll
    for (int k = 0; k < NCLASS; k++) acc[k] = bsm[k];

    const float4* ea = reinterpret_cast<const float4*>(&emb_a[(size_t)i * NCLASS]);
#pragma unroll
    for (int m4 = 0; m4 < NCLASS / 4; m4++) {
        float4 v = ea[m4];
        float vv[4] = {v.x, v.y, v.z, v.w};
#pragma unroll
        for (int q = 0; q < 4; q++) {
            float a = vv[q];
            int m = m4 * 4 + q;
#pragma unroll
            for (int k = 0; k < NCLASS; k++) acc[k] += a * wsm[m * NCLASS + k];
        }
    }

    float di = g_dinv[i];
    float s = di * (di + g_sdin[i]);
#pragma unroll
    for (int j = 0; j < OUTH; j++) {
        float h = g_Y2[(size_t)i * OUTP + j] + s * csm[j] + b2sm[j];
        h = fmaxf(h, 0.0f);
#pragma unroll
        for (int k = 0; k < NCLASS; k++) acc[k] += h * wsm[(NCLASS + j) * NCLASS + k];
    }

    float4* op = reinterpret_cast<float4*>(&out[(size_t)i * NCLASS]);
#pragma unroll
    for (int q = 0; q < NCLASS / 4; q++)
        op[q] = make_float4(acc[q * 4], acc[q * 4 + 1], acc[q * 4 + 2], acc[q * 4 + 3]);
}

// ---------------- launch ----------------
extern "C" void kernel_launch(void* const* d_in, const int* in_sizes, int n_in,
                              void* d_out, int out_size) {
    const float* x     = (const float*)d_in[0];
    const int*   ei    = (const int*)d_in[1];     // int32: JAX x64 disabled
    const float* emb_a = (const float*)d_in[2];
    const float* W1    = (const float*)d_in[3];
    const float* b1    = (const float*)d_in[4];
    const float* W2    = (const float*)d_in[5];
    const float* b2    = (const float*)d_in[6];
    const float* Wc    = (const float*)d_in[7];
    const float* bc    = (const float*)d_in[8];
    float* out = (float*)d_out;

    int n  = in_sizes[0] / INH;   // 100000
    int e  = in_sizes[1] / 2;     // 1600000
    int nh = in_sizes[4];         // 256 (b1 length)

    const int TB = 256;
    k_init <<<(n + TB - 1) / TB, TB>>>(n);
    k_w12  <<<1, 256>>>(W1, W2, b1, nh);
    k_deg  <<<(e + TB - 1) / TB, TB>>>(ei + e, e);   // dst row
    k_dinvM<<<(n + TB - 1) / TB, TB>>>(x, n);
    k_agg  <<<(e + n + TB - 1) / TB, TB>>>(0, ei, e, n);
    k_agg  <<<(e + n + TB - 1) / TB, TB>>>(1, ei, e, n);
    k_final<<<(n + TB - 1) / TB, TB>>>(emb_a, b2, Wc, bc, out, n);
}

// round 4
// speedup vs baseline: 1.0711x; 1.0711x over previous
#include <cuda_runtime.h>

#define NMAX   100000
#define EMAX   1600000
#define INH    18
#define OUTH   11
#define OUTP   12      // padded to 3x float4
#define NCLASS 40
#define CDIM   51      // NCLASS + OUTH

// ---------------- scratch (device globals; no allocs allowed) ----------------
__device__ float g_deg [NMAX];
__device__ float g_dinv[NMAX];
__device__ float g_sdin[NMAX];
__device__ __align__(16) float g_M  [NMAX * OUTP];
__device__ __align__(16) float g_Y1 [NMAX * OUTP];
__device__ __align__(16) float g_Y2 [NMAX * OUTP];
__device__ float g_nrm[EMAX];         // per-edge norm, memoized in pass 0
__device__ float g_W12[INH * OUTH];   // W1 @ W2  [18,11]
__device__ float g_c  [OUTH];         // b1 @ W2  [11]

__device__ __forceinline__ void red_add_v4(float* p, float4 v) {
    asm volatile("red.global.add.v4.f32 [%0], {%1, %2, %3, %4};"
                 :: "l"(p), "f"(v.x), "f"(v.y), "f"(v.z), "f"(v.w)
                 : "memory");
}

// ---------------- kernels ----------------

// init: only deg (self-loop = 1) and sdin. Y buffers are NOT zeroed anymore.
__global__ void k_init(int n) {
    int i = blockIdx.x * blockDim.x + threadIdx.x;
    if (i >= n) return;
    g_deg[i]  = 1.0f;
    g_sdin[i] = 0.0f;
}

// W12 = W1 @ W2 ([18,nh]@[nh,11]); c = b1 @ W2. One block.
__global__ void k_w12(const float* __restrict__ W1, const float* __restrict__ W2,
                      const float* __restrict__ b1, int nh) {
    int t = threadIdx.x;
    if (t < INH * OUTH) {
        int i = t / OUTH, j = t % OUTH;
        float s = 0.f;
        for (int k = 0; k < nh; k++) s += W1[i * nh + k] * W2[k * OUTH + j];
        g_W12[t] = s;
    } else if (t < INH * OUTH + OUTH) {
        int j = t - INH * OUTH;
        float s = 0.f;
        for (int k = 0; k < nh; k++) s += b1[k] * W2[k * OUTH + j];
        g_c[j] = s;
    }
}

// in-degree, 4 edges per thread via int4
__global__ void k_deg(const int* __restrict__ dst, int e) {
    int i = blockIdx.x * blockDim.x + threadIdx.x;
    int base = i * 4;
    if (base + 3 < e) {
        int4 d4 = *reinterpret_cast<const int4*>(dst + base);
        atomicAdd(&g_deg[d4.x], 1.0f);
        atomicAdd(&g_deg[d4.y], 1.0f);
        atomicAdd(&g_deg[d4.z], 1.0f);
        atomicAdd(&g_deg[d4.w], 1.0f);
    } else {
        for (int k = base; k < e; k++) atomicAdd(&g_deg[dst[k]], 1.0f);
    }
}

// dinv = rsqrt(deg); M = x @ W12; Y1 = di^2 * M (self-loop term, plain store)
__global__ void k_dinvM(const float* __restrict__ x, int n) {
    __shared__ float w[INH * OUTH];
    for (int t = threadIdx.x; t < INH * OUTH; t += blockDim.x) w[t] = g_W12[t];
    __syncthreads();
    int i = blockIdx.x * blockDim.x + threadIdx.x;
    if (i >= n) return;
    float di = rsqrtf(g_deg[i]);
    g_dinv[i] = di;
    float di2 = di * di;
    float xr[INH];
#pragma unroll
    for (int k = 0; k < INH; k++) xr[k] = x[i * INH + k];
    float o[OUTP];
#pragma unroll
    for (int j = 0; j < OUTH; j++) {
        float s = 0.f;
#pragma unroll
        for (int k = 0; k < INH; k++) s += xr[k] * w[k * OUTH + j];
        o[j] = s;
    }
    o[OUTH] = 0.f;
    float4* mp = reinterpret_cast<float4*>(&g_M[i * OUTP]);
    float4* yp = reinterpret_cast<float4*>(&g_Y1[i * OUTP]);
#pragma unroll
    for (int q = 0; q < 3; q++) {
        float4 v = make_float4(o[q*4], o[q*4+1], o[q*4+2], o[q*4+3]);
        mp[q] = v;
        yp[q] = make_float4(v.x * di2, v.y * di2, v.z * di2, v.w * di2);
    }
}

// pass 0: Y1 += nrm * M[s]  (edges only); memoize nrm; accumulate sdin
__global__ void k_agg0(const int* __restrict__ ei, int e) {
    int idx = blockIdx.x * blockDim.x + threadIdx.x;
    if (idx >= e) return;
    int s = ei[idx];
    int d = ei[e + idx];
    float ds = g_dinv[s];
    float nrm = ds * g_dinv[d];
    g_nrm[idx] = nrm;
    atomicAdd(&g_sdin[d], ds);
    const float4* m = reinterpret_cast<const float4*>(&g_M[(size_t)s * OUTP]);
    float4 a = m[0], b = m[1], c = m[2];
    a.x *= nrm; a.y *= nrm; a.z *= nrm; a.w *= nrm;
    b.x *= nrm; b.y *= nrm; b.z *= nrm; b.w *= nrm;
    c.x *= nrm; c.y *= nrm; c.z *= nrm; c.w *= nrm;
    float* y = &g_Y1[(size_t)d * OUTP];
    red_add_v4(y,     a);
    red_add_v4(y + 4, b);
    red_add_v4(y + 8, c);
}

// between passes: Y2 = di^2 * Y1 (self-loop of layer 2, plain store)
__global__ void k_self2(int n) {
    int i = blockIdx.x * blockDim.x + threadIdx.x;
    if (i >= n) return;
    float di = g_dinv[i];
    float di2 = di * di;
    const float4* y1 = reinterpret_cast<const float4*>(&g_Y1[i * OUTP]);
    float4* y2 = reinterpret_cast<float4*>(&g_Y2[i * OUTP]);
#pragma unroll
    for (int q = 0; q < 3; q++) {
        float4 v = y1[q];
        y2[q] = make_float4(v.x * di2, v.y * di2, v.z * di2, v.w * di2);
    }
}

// pass 1: Y2 += nrm * Y1[s]  (nrm read coalesced from memo)
__global__ void k_agg1(const int* __restrict__ ei, int e) {
    int idx = blockIdx.x * blockDim.x + threadIdx.x;
    if (idx >= e) return;
    int s = ei[idx];
    int d = ei[e + idx];
    float nrm = g_nrm[idx];
    const float4* m = reinterpret_cast<const float4*>(&g_Y1[(size_t)s * OUTP]);
    float4 a = m[0], b = m[1], c = m[2];
    a.x *= nrm; a.y *= nrm; a.z *= nrm; a.w *= nrm;
    b.x *= nrm; b.y *= nrm; b.z *= nrm; b.w *= nrm;
    c.x *= nrm; c.y *= nrm; c.z *= nrm; c.w *= nrm;
    float* y = &g_Y2[(size_t)d * OUTP];
    red_add_v4(y,     a);
    red_add_v4(y + 4, b);
    red_add_v4(y + 8, c);
}

// epilogue: emb_b = relu(Y2 + s*c + b2);  out = [emb_a, emb_b] @ Wc + bc
__global__ void k_final(const float* __restrict__ emb_a, const float* __restrict__ b2,
                        const float* __restrict__ Wc, const float* __restrict__ bc,
                        float* __restrict__ out, int n) {
    __shared__ float wsm[CDIM * NCLASS];
    __shared__ float bsm[NCLASS];
    __shared__ float csm[OUTH];
    __shared__ float b2sm[OUTH];
    for (int t = threadIdx.x; t < CDIM * NCLASS; t += blockDim.x) wsm[t] = Wc[t];
    if (threadIdx.x < NCLASS) bsm[threadIdx.x] = bc[threadIdx.x];
    if (threadIdx.x < OUTH) { csm[threadIdx.x] = g_c[threadIdx.x]; b2sm[threadIdx.x] = b2[threadIdx.x]; }
    __syncthreads();
    int i = blockIdx.x * blockDim.x + threadIdx.x;
    if (i >= n) return;

    float acc[NCLASS];
#pragma unroll
    for (int k = 0; k < NCLASS; k++) acc[k] = bsm[k];

    const float4* ea = reinterpret_cast<const float4*>(&emb_a[(size_t)i * NCLASS]);
#pragma unroll
    for (int m4 = 0; m4 < NCLASS / 4; m4++) {
        float4 v = ea[m4];
        float vv[4] = {v.x, v.y, v.z, v.w};
#pragma unroll
        for (int q = 0; q < 4; q++) {
            float a = vv[q];
            int m = m4 * 4 + q;
#pragma unroll
            for (int k = 0; k < NCLASS; k++) acc[k] += a * wsm[m * NCLASS + k];
        }
    }

    float di = g_dinv[i];
    float s = di * (di + g_sdin[i]);
#pragma unroll
    for (int j = 0; j < OUTH; j++) {
        float h = g_Y2[(size_t)i * OUTP + j] + s * csm[j] + b2sm[j];
        h = fmaxf(h, 0.0f);
#pragma unroll
        for (int k = 0; k < NCLASS; k++) acc[k] += h * wsm[(NCLASS + j) * NCLASS + k];
    }

    float4* op = reinterpret_cast<float4*>(&out[(size_t)i * NCLASS]);
#pragma unroll
    for (int q = 0; q < NCLASS / 4; q++)
        op[q] = make_float4(acc[q * 4], acc[q * 4 + 1], acc[q * 4 + 2], acc[q * 4 + 3]);
}

// ---------------- launch ----------------
extern "C" void kernel_launch(void* const* d_in, const int* in_sizes, int n_in,
                              void* d_out, int out_size) {
    const float* x     = (const float*)d_in[0];
    const int*   ei    = (const int*)d_in[1];     // int32 (JAX x64 disabled)
    const float* emb_a = (const float*)d_in[2];
    const float* W1    = (const float*)d_in[3];
    const float* b1    = (const float*)d_in[4];
    const float* W2    = (const float*)d_in[5];
    const float* b2    = (const float*)d_in[6];
    const float* Wc    = (const float*)d_in[7];
    const float* bc    = (const float*)d_in[8];
    float* out = (float*)d_out;

    int n  = in_sizes[0] / INH;   // 100000
    int e  = in_sizes[1] / 2;     // 1600000
    int nh = in_sizes[4];         // 256 (b1 length)

    const int TB = 256;
    k_init <<<(n + TB - 1) / TB, TB>>>(n);
    k_w12  <<<1, 256>>>(W1, W2, b1, nh);
    k_deg  <<<(e / 4 + TB - 1) / TB, TB>>>(ei + e, e);   // dst row
    k_dinvM<<<(n + TB - 1) / TB, TB>>>(x, n);
    k_agg0 <<<(e + TB - 1) / TB, TB>>>(ei, e);
    k_self2<<<(n + TB - 1) / TB, TB>>>(n);
    k_agg1 <<<(e + TB - 1) / TB, TB>>>(ei, e);
    k_final<<<(n + TB - 1) / TB, TB>>>(emb_a, b2, Wc, bc, out, n);
}